// round 5
// baseline (speedup 1.0000x reference)
#include <cuda_runtime.h>
#include <cuda_bf16.h>
#include <cstddef>

#define ROWS   128
#define T      30
#define OUT_T  26
#define NPAIRS 8256
#define NTHREADS 256
#define NWARPS   8
#define GSEG     2          // CTAs per batch
#define UNITS    320        // 10 tiles * 32 i-iterations
#define UPW      (UNITS / (GSEG * NWARPS))   // 20 units per warp

#define XS_STRIDE 36        // 144 B rows: 16B-aligned for float4 broadcast loads
#define STG_STRIDE 33       // k-major staging stride (odd -> conflict-free)
#define STG_WORDS (OUT_T * STG_STRIDE)   // 858

__device__ __forceinline__ int pair_offset(int i) {
    return i * ROWS - (i * (i - 1)) / 2;
}

__device__ __forceinline__ int div26(int w) {   // exact floor(w/26) for 0<=w<832
    return (w * 10083) >> 18;
}

__global__ __launch_bounds__(NTHREADS, 3)
void ts_cov_kernel(const float* __restrict__ in, float* __restrict__ out) {
    const int batch = blockIdx.x;
    const int seg   = blockIdx.y;

    __shared__ float xs[ROWS * XS_STRIDE];          // 18432 B
    __shared__ float stage[NWARPS * STG_WORDS];     // 27456 B (doubles as raw staging)

    // ---- Stage raw input (coalesced) ----
    const float* gin = in + (size_t)batch * (ROWS * T);
    for (int idx = threadIdx.x; idx < ROWS * T; idx += NTHREADS)
        stage[idx] = gin[idx];
    __syncthreads();

    // ---- Per-row normalization (population std) ----
    if (threadIdx.x < ROWS) {
        const int r = threadIdx.x;
        float s = 0.f;
#pragma unroll
        for (int t = 0; t < T; t++) s += stage[r * T + t];
        const float mean = s * (1.0f / T);
        float v = 0.f;
#pragma unroll
        for (int t = 0; t < T; t++) {
            float c = stage[r * T + t] - mean;
            v += c * c;
        }
        const float inv = rsqrtf(v * (1.0f / T));
#pragma unroll
        for (int t = 0; t < T; t++)
            xs[r * XS_STRIDE + t] = (stage[r * T + t] - mean) * inv;
    }
    __syncthreads();   // xs ready; stage[] reused as per-warp staging

    const int wid  = threadIdx.x >> 5;
    const int lane = threadIdx.x & 31;
    const int gw   = seg * NWARPS + wid;        // global warp id within batch
    float* sw = stage + wid * STG_WORDS;
    float* gout = out + (size_t)batch * ((size_t)NPAIRS * OUT_T);

    const int uA = gw * UPW;
    const int uB = uA + UPW;

    for (int tile = (uA >> 5); tile <= ((uB - 1) >> 5); ++tile) {
        // tile -> (jb, is), triangular enumeration with is <= jb
        const int jb = (tile >= 6) ? 3 : (tile >= 3) ? 2 : (tile >= 1) ? 1 : 0;
        const int is = tile - (jb * (jb + 1)) / 2;
        const int j0 = jb * 32;

        // b row (j0+lane) register-resident for this tile (float4 loads)
        float b[T];
        {
            const float4* bp = (const float4*)(xs + (j0 + lane) * XS_STRIDE);
#pragma unroll
            for (int m = 0; m < 7; m++) {
                float4 v4 = bp[m];
                b[m * 4 + 0] = v4.x; b[m * 4 + 1] = v4.y;
                b[m * 4 + 2] = v4.z; b[m * 4 + 3] = v4.w;
            }
            float2 v2 = *(const float2*)(xs + (j0 + lane) * XS_STRIDE + 28);
            b[28] = v2.x; b[29] = v2.y;
        }

        const int loU = max(uA, tile * 32);
        const int hiU = min(uB, tile * 32 + 32);

        for (int u = loU; u < hiU; ++u) {
            const int i = is * 32 + (u - tile * 32);

            // Broadcast-load row i (8 wavefronts), form products
            float p[T];
            {
                const float4* ap = (const float4*)(xs + i * XS_STRIDE);
#pragma unroll
                for (int m = 0; m < 7; m++) {
                    float4 v4 = ap[m];
                    p[m * 4 + 0] = v4.x * b[m * 4 + 0];
                    p[m * 4 + 1] = v4.y * b[m * 4 + 1];
                    p[m * 4 + 2] = v4.z * b[m * 4 + 2];
                    p[m * 4 + 3] = v4.w * b[m * 4 + 3];
                }
                float2 v2 = *(const float2*)(xs + i * XS_STRIDE + 28);
                p[28] = v2.x * b[28];
                p[29] = v2.y * b[29];
            }

            // Sliding window of 5, staged k-major: sw[k*33 + lane]
            float s = p[0] + p[1] + p[2] + p[3] + p[4];
            sw[lane] = s * 0.2f;
#pragma unroll
            for (int k = 1; k < OUT_T; k++) {
                s += p[k + 4] - p[k - 1];
                sw[k * STG_STRIDE + lane] = s * 0.2f;
            }
            __syncwarp();

            // Coalesced streaming copy-out
            const int lo = (i > j0) ? (i - j0) : 0;
            const size_t p_start = (size_t)pair_offset(i) + (size_t)(j0 + lo - i);
            float* basep = gout + p_start * OUT_T;

            if (lo == 0) {
                // full tile: 832 floats = 416 float2, exactly 13 warp batches.
                // w = 2*(m*32+lane): even, q = w/26, k = w-26q even <= 24,
                // so (k, k+1) always share q -> two conflict-free LDS.
#pragma unroll
                for (int m = 0; m < 13; m++) {
                    const int w = 2 * (m * 32 + lane);
                    const int q = div26(w);
                    const int k = w - q * OUT_T;
                    float2 v = make_float2(sw[k * STG_STRIDE + q],
                                           sw[(k + 1) * STG_STRIDE + q]);
                    __stcs((float2*)(basep + w), v);
                }
            } else {
                const int total = (32 - lo) * OUT_T;
#pragma unroll
                for (int m = 0; m < OUT_T; m++) {
                    const int w = m * 32 + lane;
                    if (w < total) {
                        const int q = div26(w);
                        const int k = w - q * OUT_T;
                        __stcs(basep + w, sw[k * STG_STRIDE + lo + q]);
                    }
                }
            }
            __syncwarp();   // protect sw before next iteration's STS
        }
    }
}

extern "C" void kernel_launch(void* const* d_in, const int* in_sizes, int n_in,
                              void* d_out, int out_size) {
    const float* in = (const float*)d_in[0];
    float* out = (float*)d_out;
    const int B = in_sizes[0] / (ROWS * T);
    dim3 grid(B, GSEG);
    ts_cov_kernel<<<grid, NTHREADS>>>(in, out);
}